// round 5
// baseline (speedup 1.0000x reference)
#include <cuda_runtime.h>
#include <cstdint>
#include <math.h>

// LSTMCell fused via mma.sync tf32 (m16n8k8) GEMMs — compute_103-safe PTX.
//   gates = [x|h] @ Wt1^T + bias             (K=1024, N=2048)
//   s     = sigmoid([x|me] @ Wt2^T + mb)*me  (K=2048, N=1536)
//   t     = s @ Wt3^T ; LSTM epilogue        (K=1536, N=512)
// 3-stage circular SMEM pipeline, ONE __syncthreads per BK=32 stage.
// B tiles: cp.async double-lookahead. A tiles: register-staged + cvt.rna.tf32.

#define BATCH 16384

// ---------------- scratch (__device__ globals: no allocations allowed) ----
__device__ float g_gates[(size_t)BATCH * 2048];        // 128 MiB
__device__ float g_s[(size_t)BATCH * 1536];            //  96 MiB
__device__ float g_Wt1[(size_t)2048 * 1024];           // [n][k] K-major
__device__ float g_Wt2[(size_t)1536 * 2048];
__device__ float g_Wt3[(size_t)512 * 1536];

__device__ __forceinline__ float rna_tf32(float x) {
    float r; asm("cvt.rna.tf32.f32 %0, %1;" : "=f"(r) : "f"(x)); return r;
}
__device__ __forceinline__ float sigf(float x) { return 1.0f / (1.0f + __expf(-x)); }
__device__ __forceinline__ float tanh_(float x) { return 2.0f * sigf(2.0f * x) - 1.0f; }

__device__ __forceinline__ void mma_tf32(float& c0, float& c1, float& c2, float& c3,
                                         uint32_t a0, uint32_t a1, uint32_t a2, uint32_t a3,
                                         uint32_t b0, uint32_t b1) {
    asm volatile(
        "mma.sync.aligned.m16n8k8.row.col.f32.tf32.tf32.f32 "
        "{%0,%1,%2,%3}, {%4,%5,%6,%7}, {%8,%9}, {%0,%1,%2,%3};"
        : "+f"(c0), "+f"(c1), "+f"(c2), "+f"(c3)
        : "r"(a0), "r"(a1), "r"(a2), "r"(a3), "r"(b0), "r"(b1));
}

#define CP_ASYNC16(dst_u32, src_ptr) \
    asm volatile("cp.async.cg.shared.global [%0], [%1], 16;" \
                 :: "r"(dst_u32), "l"(src_ptr))
#define CP_COMMIT() asm volatile("cp.async.commit_group;")
#define CP_WAIT1()  asm volatile("cp.async.wait_group 1;" ::: "memory")
#define CP_WAIT0()  asm volatile("cp.async.wait_group 0;" ::: "memory")

// ---------------- merged weight transpose + tf32 rounding pre-pass --------
// One kernel, flat grid, 5 jobs. transpose src[R][C] -> dst[C][dstStride].
__device__ __forceinline__ void tr_body(const float* __restrict__ src,
                                        float* __restrict__ dst,
                                        int C, int dstStride, int bx, int by) {
    __shared__ float t[32][33];
    const int c0 = bx << 5, r0 = by << 5;
    const int tx = threadIdx.x, ty = threadIdx.y;
#pragma unroll
    for (int j = ty; j < 32; j += 8)
        t[j][tx] = rna_tf32(src[(size_t)(r0 + j) * C + c0 + tx]);
    __syncthreads();
#pragma unroll
    for (int j = ty; j < 32; j += 8)
        dst[(size_t)(c0 + j) * dstStride + r0 + tx] = t[tx][j];
}

__global__ void __launch_bounds__(256) transpose_all(
    const float* __restrict__ W_ih,  const float* __restrict__ W_hh,
    const float* __restrict__ W_memi, const float* __restrict__ W_memh,
    const float* __restrict__ W_memt)
{
    int id = blockIdx.x;
    // job block counts: 1024,1024,768,2304,768 ; cum: 1024,2048,2816,5120,5888
    if (id < 1024)      tr_body(W_ih,   g_Wt1,        2048, 1024, id % 64, id / 64);
    else if (id < 2048) { id -= 1024; tr_body(W_hh,   g_Wt1 + 512, 2048, 1024, id % 64, id / 64); }
    else if (id < 2816) { id -= 2048; tr_body(W_memi, g_Wt2,       1536, 2048, id % 48, id / 48); }
    else if (id < 5120) { id -= 2816; tr_body(W_memh, g_Wt2 + 512, 1536, 2048, id % 48, id / 48); }
    else                { id -= 5120; tr_body(W_memt, g_Wt3,        512, 1536, id % 16, id / 16); }
}

// ---------------- main GEMM ------------------------------------------------
// Tile 128x128, BK=32, 8 warps (2M x 4N), each warp 64x32 = 4x4 m16n8k8.
// 3 SMEM stages, each A[128][36] + B[128][36] floats.
#define PAD 36
#define TILE_F (128 * PAD)
#define STAGE_F (2 * TILE_F)
#define SMEM_BYTES (3 * STAGE_F * 4)   // 110592

template <int MODE>
__global__ void __launch_bounds__(256, 2) mma_gemm(
    const float* __restrict__ A0, int lda0,
    const float* __restrict__ A1, int lda1,
    int K0, int K,
    const float* __restrict__ Wt,
    const float* __restrict__ bias,
    const float* __restrict__ me,
    const float* __restrict__ cin, const float* __restrict__ hin,
    float* __restrict__ outp)
{
    extern __shared__ float smem[];           // [3 stage][A|B][TILE_F]
    const uint32_t sbase = (uint32_t)__cvta_generic_to_shared(smem);
    const int tid = threadIdx.x, wid = tid >> 5, lane = tid & 31;
    const int bm = blockIdx.y << 7, bn = blockIdx.x << 7;
    const int wm = (wid >> 2) << 6;
    const int wn = (wid & 3) << 5;
    const int grp = lane >> 2, qd = lane & 3;

    const float* as0 = (MODE == 2) ? (const float*)g_s : A0;
    const float* as1 = (MODE == 2) ? (const float*)g_s : A1;

    float acc[4][4][4];
#pragma unroll
    for (int mt = 0; mt < 4; mt++)
#pragma unroll
        for (int nt = 0; nt < 4; nt++)
#pragma unroll
            for (int q = 0; q < 4; q++) acc[mt][nt][q] = 0.0f;

    const int nst = K >> 5;
    float4 aR[4];

    // staging map: i = tid + t*256 -> row = i>>3, q4 = (i&7)*4
#define LDG_A(S) do {                                                           \
    const int _k0 = (S) << 5;                                                   \
    _Pragma("unroll")                                                           \
    for (int t = 0; t < 4; t++) {                                               \
        const int i = tid + (t << 8);                                           \
        const int row = i >> 3, q4 = (i & 7) << 2;                              \
        const int ka = _k0 + q4;                                                \
        const float* pa = (ka < K0)                                             \
            ? as0 + (size_t)(bm + row) * lda0 + ka                              \
            : as1 + (size_t)(bm + row) * lda1 + (ka - K0);                      \
        aR[t] = *(const float4*)pa;                                             \
    } } while (0)

#define STS_A(BUF) do {                                                         \
    float* dA = smem + (BUF) * STAGE_F;                                         \
    _Pragma("unroll")                                                           \
    for (int t = 0; t < 4; t++) {                                               \
        const int i = tid + (t << 8);                                           \
        const int off = (i >> 3) * PAD + ((i & 7) << 2);                        \
        float4 a = aR[t];                                                       \
        a.x = rna_tf32(a.x); a.y = rna_tf32(a.y);                               \
        a.z = rna_tf32(a.z); a.w = rna_tf32(a.w);                               \
        *(float4*)(dA + off) = a;                                               \
    } } while (0)

#define ISSUE_B(S, BUF) do {                                                    \
    const int _k0 = (S) << 5;                                                   \
    _Pragma("unroll")                                                           \
    for (int t = 0; t < 4; t++) {                                               \
        const int i = tid + (t << 8);                                           \
        const int row = i >> 3, q4 = (i & 7) << 2;                              \
        const uint32_t d = sbase +                                              \
            (uint32_t)((((BUF) * STAGE_F) + TILE_F + row * PAD + q4) << 2);     \
        CP_ASYNC16(d, Wt + (size_t)(bn + row) * K + _k0 + q4);                  \
    }                                                                           \
    CP_COMMIT(); } while (0)

    // prologue: stages 0,1 fully staged; stage-2 A held in regs, B deferred.
    LDG_A(0); STS_A(0); ISSUE_B(0, 0);
    LDG_A(1); STS_A(1); ISSUE_B(1, 1);
    if (nst > 2) LDG_A(2);

    int buf = 0;            // buf = s % 3
    for (int s = 0; s < nst; s++) {
        if (s + 1 < nst) CP_WAIT1(); else CP_WAIT0();
        __syncthreads();

        const int wbuf = (buf + 2 >= 3) ? buf - 1 : buf + 2;   // (s+2)%3
        if (s + 2 < nst) { ISSUE_B(s + 2, wbuf); STS_A(wbuf); }
        if (s + 3 < nst) LDG_A(s + 3);

        const float* As = smem + buf * STAGE_F;
        const float* Bs = As + TILE_F;
#pragma unroll
        for (int kk = 0; kk < 4; kk++) {
            const int kb = (kk << 3) + qd;
            uint32_t af[4][4];
#pragma unroll
            for (int mt = 0; mt < 4; mt++) {
                const int base = (wm + (mt << 4) + grp) * PAD + kb;
                af[mt][0] = __float_as_uint(As[base]);
                af[mt][1] = __float_as_uint(As[base + 8 * PAD]);
                af[mt][2] = __float_as_uint(As[base + 4]);
                af[mt][3] = __float_as_uint(As[base + 8 * PAD + 4]);
            }
            uint32_t bf[4][2];
#pragma unroll
            for (int nt = 0; nt < 4; nt++) {
                const int base = (wn + (nt << 3) + grp) * PAD + kb;
                bf[nt][0] = __float_as_uint(Bs[base]);
                bf[nt][1] = __float_as_uint(Bs[base + 4]);
            }
#pragma unroll
            for (int mt = 0; mt < 4; mt++)
#pragma unroll
                for (int nt = 0; nt < 4; nt++)
                    mma_tf32(acc[mt][nt][0], acc[mt][nt][1],
                             acc[mt][nt][2], acc[mt][nt][3],
                             af[mt][0], af[mt][1], af[mt][2], af[mt][3],
                             bf[nt][0], bf[nt][1]);
        }
        buf = (buf + 1 >= 3) ? 0 : buf + 1;
    }

    // ---- fused epilogues (c frag rows grp/grp+8, cols 2qd/2qd+1) ----
#pragma unroll
    for (int mt = 0; mt < 4; mt++) {
#pragma unroll
        for (int nt = 0; nt < 4; nt++) {
#pragma unroll
            for (int hrow = 0; hrow < 2; hrow++) {
                const int r = bm + wm + (mt << 4) + grp + (hrow << 3);
                const int cc = bn + wn + (nt << 3) + (qd << 1);
                const float v0 = acc[mt][nt][hrow * 2];
                const float v1 = acc[mt][nt][hrow * 2 + 1];
                if (MODE == 0) {
                    const float2 b2 = *(const float2*)(bias + cc);
                    float2 o = {v0 + b2.x, v1 + b2.y};
                    *(float2*)(g_gates + (size_t)r * 2048 + cc) = o;
                } else if (MODE == 1) {
                    const float2 b2 = *(const float2*)(bias + cc);
                    const float2 m2 = *(const float2*)(me + (size_t)r * 1536 + cc);
                    float2 o = {sigf(v0 + b2.x) * m2.x, sigf(v1 + b2.y) * m2.y};
                    *(float2*)(g_s + (size_t)r * 1536 + cc) = o;
                } else {
                    const size_t gb = (size_t)r * 2048 + cc;
                    const float2 f2 = *(const float2*)(g_gates + gb);
                    const float2 i2 = *(const float2*)(g_gates + gb + 512);
                    const float2 o2 = *(const float2*)(g_gates + gb + 1024);
                    const float2 g2 = *(const float2*)(g_gates + gb + 1536);
                    const float2 c2 = *(const float2*)(cin + (size_t)r * 512 + cc);
                    const float2 h2 = *(const float2*)(hin + (size_t)r * 512 + cc);
                    float2 oh, oc;
                    {
                        float cn = sigf(f2.x) * c2.x + sigf(i2.x) * tanh_(g2.x) + v0;
                        float hn = sigf(o2.x) * tanh_(cn);
                        oh.x = 0.8f * hn + 0.2f * h2.x;
                        oc.x = 0.8f * cn + 0.2f * c2.x;
                    }
                    {
                        float cn = sigf(f2.y) * c2.y + sigf(i2.y) * tanh_(g2.y) + v1;
                        float hn = sigf(o2.y) * tanh_(cn);
                        oh.y = 0.8f * hn + 0.2f * h2.y;
                        oc.y = 0.8f * cn + 0.2f * c2.y;
                    }
                    *(float2*)(outp + (size_t)r * 512 + cc) = oh;
                    *(float2*)(outp + (size_t)BATCH * 512 + (size_t)r * 512 + cc) = oc;
                }
            }
        }
    }
}

// ---------------- host ----------------------------------------------------
extern "C" void kernel_launch(void* const* d_in, const int* in_sizes, int n_in,
                              void* d_out, int out_size)
{
    const float* x      = (const float*)d_in[0];
    const float* h      = (const float*)d_in[1];
    const float* c      = (const float*)d_in[2];
    const float* me     = (const float*)d_in[3];
    const float* W_ih   = (const float*)d_in[4];
    const float* W_hh   = (const float*)d_in[5];
    const float* bias   = (const float*)d_in[6];
    const float* W_memi = (const float*)d_in[7];
    const float* W_memh = (const float*)d_in[8];
    const float* W_memt = (const float*)d_in[9];
    const float* mem_b  = (const float*)d_in[10];
    float* out = (float*)d_out;

    cudaFuncSetAttribute(mma_gemm<0>, cudaFuncAttributeMaxDynamicSharedMemorySize, SMEM_BYTES);
    cudaFuncSetAttribute(mma_gemm<1>, cudaFuncAttributeMaxDynamicSharedMemorySize, SMEM_BYTES);
    cudaFuncSetAttribute(mma_gemm<2>, cudaFuncAttributeMaxDynamicSharedMemorySize, SMEM_BYTES);

    float *wt1, *wt2, *wt3;
    cudaGetSymbolAddress((void**)&wt1, g_Wt1);
    cudaGetSymbolAddress((void**)&wt2, g_Wt2);
    cudaGetSymbolAddress((void**)&wt3, g_Wt3);

    transpose_all<<<5888, dim3(32, 8)>>>(W_ih, W_hh, W_memi, W_memh, W_memt);

    mma_gemm<0><<<dim3(16, 128), 256, SMEM_BYTES>>>(
        x, 512, h, 512, 512, 1024, wt1, bias, nullptr, nullptr, nullptr, nullptr);

    mma_gemm<1><<<dim3(12, 128), 256, SMEM_BYTES>>>(
        x, 512, me, 1536, 512, 2048, wt2, mem_b, me, nullptr, nullptr, nullptr);

    mma_gemm<2><<<dim3(4, 128), 256, SMEM_BYTES>>>(
        nullptr, 1536, nullptr, 1536, 1536, 1536, wt3, nullptr, nullptr, c, h, out);
}

// round 6
// speedup vs baseline: 1.3608x; 1.3608x over previous
#include <cuda_runtime.h>
#include <cstdint>
#include <math.h>

// LSTMCell fused via mma.sync tf32 (m16n8k8) GEMMs — compute_103-safe PTX.
//   gates = [x|h] @ Wt1^T + bias             (K=1024, N=2048)
//   s     = sigmoid([x|me] @ Wt2^T + mb)*me  (K=2048, N=1536)
//   t     = s @ Wt3^T ; LSTM epilogue        (K=1536, N=512)
// Double-buffered SMEM (R4 skeleton) + ldmatrix.x4 fragment loading.

#define BATCH 16384

// ---------------- scratch (__device__ globals: no allocations allowed) ----
__device__ float g_gates[(size_t)BATCH * 2048];        // 128 MiB
__device__ float g_s[(size_t)BATCH * 1536];            //  96 MiB
__device__ float g_Wt1[(size_t)2048 * 1024];           // [n][k] K-major
__device__ float g_Wt2[(size_t)1536 * 2048];
__device__ float g_Wt3[(size_t)512 * 1536];

__device__ __forceinline__ float rna_tf32(float x) {
    float r; asm("cvt.rna.tf32.f32 %0, %1;" : "=f"(r) : "f"(x)); return r;
}
__device__ __forceinline__ float sigf(float x) { return 1.0f / (1.0f + __expf(-x)); }
__device__ __forceinline__ float tanh_(float x) { return 2.0f * sigf(2.0f * x) - 1.0f; }

__device__ __forceinline__ void mma_tf32(float& c0, float& c1, float& c2, float& c3,
                                         uint32_t a0, uint32_t a1, uint32_t a2, uint32_t a3,
                                         uint32_t b0, uint32_t b1) {
    asm volatile(
        "mma.sync.aligned.m16n8k8.row.col.f32.tf32.tf32.f32 "
        "{%0,%1,%2,%3}, {%4,%5,%6,%7}, {%8,%9}, {%0,%1,%2,%3};"
        : "+f"(c0), "+f"(c1), "+f"(c2), "+f"(c3)
        : "r"(a0), "r"(a1), "r"(a2), "r"(a3), "r"(b0), "r"(b1));
}

__device__ __forceinline__ void ldsm_x4(uint32_t& r0, uint32_t& r1,
                                        uint32_t& r2, uint32_t& r3, uint32_t addr) {
    asm volatile("ldmatrix.sync.aligned.m8n8.x4.shared.b16 {%0,%1,%2,%3}, [%4];"
                 : "=r"(r0), "=r"(r1), "=r"(r2), "=r"(r3) : "r"(addr));
}

#define CP_ASYNC16(dst_u32, src_ptr) \
    asm volatile("cp.async.cg.shared.global [%0], [%1], 16;" \
                 :: "r"(dst_u32), "l"(src_ptr))
#define CP_COMMIT() asm volatile("cp.async.commit_group;")
#define CP_WAIT1()  asm volatile("cp.async.wait_group 1;" ::: "memory")
#define CP_WAIT0()  asm volatile("cp.async.wait_group 0;" ::: "memory")

// ---------------- merged weight transpose + tf32 rounding pre-pass --------
__device__ __forceinline__ void tr_body(const float* __restrict__ src,
                                        float* __restrict__ dst,
                                        int C, int dstStride, int bx, int by) {
    __shared__ float t[32][33];
    const int c0 = bx << 5, r0 = by << 5;
    const int tx = threadIdx.x, ty = threadIdx.y;
#pragma unroll
    for (int j = ty; j < 32; j += 8)
        t[j][tx] = rna_tf32(src[(size_t)(r0 + j) * C + c0 + tx]);
    __syncthreads();
#pragma unroll
    for (int j = ty; j < 32; j += 8)
        dst[(size_t)(c0 + j) * dstStride + r0 + tx] = t[tx][j];
}

__global__ void __launch_bounds__(256) transpose_all(
    const float* __restrict__ W_ih,  const float* __restrict__ W_hh,
    const float* __restrict__ W_memi, const float* __restrict__ W_memh,
    const float* __restrict__ W_memt)
{
    int id = blockIdx.x;
    if (id < 1024)      tr_body(W_ih,   g_Wt1,        2048, 1024, id % 64, id / 64);
    else if (id < 2048) { id -= 1024; tr_body(W_hh,   g_Wt1 + 512, 2048, 1024, id % 64, id / 64); }
    else if (id < 2816) { id -= 2048; tr_body(W_memi, g_Wt2,       1536, 2048, id % 48, id / 48); }
    else if (id < 5120) { id -= 2816; tr_body(W_memh, g_Wt2 + 512, 1536, 2048, id % 48, id / 48); }
    else                { id -= 5120; tr_body(W_memt, g_Wt3,        512, 1536, id % 16, id / 16); }
}

// ---------------- main GEMM ------------------------------------------------
// Tile 128x128, BK=32, 8 warps (2M x 4N), each warp 64x32 = 4x4 m16n8k8.
// Double-buffered: [2][A|B][128][36] floats.
#define PAD 36
#define TILE_F (128 * PAD)
#define STAGE_F (2 * TILE_F)
#define SMEM_BYTES (2 * STAGE_F * 4)   // 73728

template <int MODE>
__global__ void __launch_bounds__(256, 2) mma_gemm(
    const float* __restrict__ A0, int lda0,
    const float* __restrict__ A1, int lda1,
    int K0, int K,
    const float* __restrict__ Wt,
    const float* __restrict__ bias,
    const float* __restrict__ me,
    const float* __restrict__ cin, const float* __restrict__ hin,
    float* __restrict__ outp)
{
    extern __shared__ float smem[];           // [2 buf][A|B][TILE_F]
    const uint32_t sbase = (uint32_t)__cvta_generic_to_shared(smem);
    const int tid = threadIdx.x, wid = tid >> 5, lane = tid & 31;
    const int bm = blockIdx.y << 7, bn = blockIdx.x << 7;
    const int wm = (wid >> 2) << 6;
    const int wn = (wid & 3) << 5;
    const int grp = lane >> 2, qd = lane & 3;

    const float* as0 = (MODE == 2) ? (const float*)g_s : A0;
    const float* as1 = (MODE == 2) ? (const float*)g_s : A1;

    float acc[4][4][4];
#pragma unroll
    for (int mt = 0; mt < 4; mt++)
#pragma unroll
        for (int nt = 0; nt < 4; nt++)
#pragma unroll
            for (int q = 0; q < 4; q++) acc[mt][nt][q] = 0.0f;

    const int nst = K >> 5;
    float4 aR[4];

    // ldmatrix per-lane addresses (byte offsets within a buffer):
    //  A x4 (per mt): m0 rows 0-7 b0-15 | m1 rows 8-15 b0-15 | m2 rows 0-7 b16-31 | m3 rows 8-15 b16-31
    const int l7 = lane & 7;
    const uint32_t a_off =
        (uint32_t)(((wm + l7 + (((lane >> 3) & 1) << 3)) * PAD) << 2) +
        (uint32_t)((((lane >> 4) & 1)) << 4);
    //  B x4 (per nt-pair p2): m0 n0-7 b0-15 | m1 n0-7 b16-31 | m2 n8-15 b0-15 | m3 n8-15 b16-31
    const uint32_t b_off = (uint32_t)(TILE_F << 2) +
        (uint32_t)(((wn + (((lane >> 4) & 1) << 3) + l7) * PAD) << 2) +
        (uint32_t)((((lane >> 3) & 1)) << 4);

    // staging map: i = tid + t*256 -> row = i>>3, q4 = (i&7)*4
#define LDG_A(S) do {                                                           \
    const int _k0 = (S) << 5;                                                   \
    _Pragma("unroll")                                                           \
    for (int t = 0; t < 4; t++) {                                               \
        const int i = tid + (t << 8);                                           \
        const int row = i >> 3, q4 = (i & 7) << 2;                              \
        const int ka = _k0 + q4;                                                \
        const float* pa = (ka < K0)                                             \
            ? as0 + (size_t)(bm + row) * lda0 + ka                              \
            : as1 + (size_t)(bm + row) * lda1 + (ka - K0);                      \
        aR[t] = *(const float4*)pa;                                             \
    } } while (0)

#define STS_A(BUF) do {                                                         \
    float* dA = smem + (BUF) * STAGE_F;                                         \
    _Pragma("unroll")                                                           \
    for (int t = 0; t < 4; t++) {                                               \
        const int i = tid + (t << 8);                                           \
        const int off = (i >> 3) * PAD + ((i & 7) << 2);                        \
        float4 a = aR[t];                                                       \
        a.x = rna_tf32(a.x); a.y = rna_tf32(a.y);                               \
        a.z = rna_tf32(a.z); a.w = rna_tf32(a.w);                               \
        *(float4*)(dA + off) = a;                                               \
    } } while (0)

#define ISSUE_B(S, BUF) do {                                                    \
    const int _k0 = (S) << 5;                                                   \
    _Pragma("unroll")                                                           \
    for (int t = 0; t < 4; t++) {                                               \
        const int i = tid + (t << 8);                                           \
        const int row = i >> 3, q4 = (i & 7) << 2;                              \
        const uint32_t d = sbase +                                              \
            (uint32_t)((((BUF) * STAGE_F) + TILE_F + row * PAD + q4) << 2);     \
        CP_ASYNC16(d, Wt + (size_t)(bn + row) * K + _k0 + q4);                  \
    }                                                                           \
    CP_COMMIT(); } while (0)

    LDG_A(0); STS_A(0); ISSUE_B(0, 0);
    LDG_A(1); STS_A(1); ISSUE_B(1, 1);

    for (int s = 0; s < nst; s++) {
        const int p = s & 1;
        if (s + 1 < nst) CP_WAIT1(); else CP_WAIT0();
        __syncthreads();
        if (s + 2 < nst) LDG_A(s + 2);

        const uint32_t abuf = sbase + (uint32_t)((p * STAGE_F) << 2) + a_off;
        const uint32_t bbuf = sbase + (uint32_t)((p * STAGE_F) << 2) + b_off;
#pragma unroll
        for (int kk = 0; kk < 4; kk++) {
            uint32_t af[4][4];
#pragma unroll
            for (int mt = 0; mt < 4; mt++)
                ldsm_x4(af[mt][0], af[mt][1], af[mt][2], af[mt][3],
                        abuf + (uint32_t)(mt * (16 * PAD * 4)) + (uint32_t)(kk * 32));
            uint32_t bf[4][2];
#pragma unroll
            for (int p2 = 0; p2 < 2; p2++)
                ldsm_x4(bf[2 * p2][0], bf[2 * p2][1], bf[2 * p2 + 1][0], bf[2 * p2 + 1][1],
                        bbuf + (uint32_t)(p2 * (16 * PAD * 4)) + (uint32_t)(kk * 32));
#pragma unroll
            for (int mt = 0; mt < 4; mt++)
#pragma unroll
                for (int nt = 0; nt < 4; nt++)
                    mma_tf32(acc[mt][nt][0], acc[mt][nt][1],
                             acc[mt][nt][2], acc[mt][nt][3],
                             af[mt][0], af[mt][1], af[mt][2], af[mt][3],
                             bf[nt][0], bf[nt][1]);
        }

        __syncthreads();
        if (s + 2 < nst) { STS_A((s + 2) & 1); ISSUE_B(s + 2, p); }
    }

    // ---- fused epilogues (c frag rows grp/grp+8, cols 2qd/2qd+1) ----
#pragma unroll
    for (int mt = 0; mt < 4; mt++) {
#pragma unroll
        for (int nt = 0; nt < 4; nt++) {
#pragma unroll
            for (int hrow = 0; hrow < 2; hrow++) {
                const int r = bm + wm + (mt << 4) + grp + (hrow << 3);
                const int cc = bn + wn + (nt << 3) + (qd << 1);
                const float v0 = acc[mt][nt][hrow * 2];
                const float v1 = acc[mt][nt][hrow * 2 + 1];
                if (MODE == 0) {
                    const float2 b2 = *(const float2*)(bias + cc);
                    float2 o = {v0 + b2.x, v1 + b2.y};
                    *(float2*)(g_gates + (size_t)r * 2048 + cc) = o;
                } else if (MODE == 1) {
                    const float2 b2 = *(const float2*)(bias + cc);
                    const float2 m2 = *(const float2*)(me + (size_t)r * 1536 + cc);
                    float2 o = {sigf(v0 + b2.x) * m2.x, sigf(v1 + b2.y) * m2.y};
                    *(float2*)(g_s + (size_t)r * 1536 + cc) = o;
                } else {
                    const size_t gb = (size_t)r * 2048 + cc;
                    const float2 f2 = *(const float2*)(g_gates + gb);
                    const float2 i2 = *(const float2*)(g_gates + gb + 512);
                    const float2 o2 = *(const float2*)(g_gates + gb + 1024);
                    const float2 g2 = *(const float2*)(g_gates + gb + 1536);
                    const float2 c2 = *(const float2*)(cin + (size_t)r * 512 + cc);
                    const float2 h2 = *(const float2*)(hin + (size_t)r * 512 + cc);
                    float2 oh, oc;
                    {
                        float cn = sigf(f2.x) * c2.x + sigf(i2.x) * tanh_(g2.x) + v0;
                        float hn = sigf(o2.x) * tanh_(cn);
                        oh.x = 0.8f * hn + 0.2f * h2.x;
                        oc.x = 0.8f * cn + 0.2f * c2.x;
                    }
                    {
                        float cn = sigf(f2.y) * c2.y + sigf(i2.y) * tanh_(g2.y) + v1;
                        float hn = sigf(o2.y) * tanh_(cn);
                        oh.y = 0.8f * hn + 0.2f * h2.y;
                        oc.y = 0.8f * cn + 0.2f * c2.y;
                    }
                    *(float2*)(outp + (size_t)r * 512 + cc) = oh;
                    *(float2*)(outp + (size_t)BATCH * 512 + (size_t)r * 512 + cc) = oc;
                }
            }
        }
    }
}

// ---------------- host ----------------------------------------------------
extern "C" void kernel_launch(void* const* d_in, const int* in_sizes, int n_in,
                              void* d_out, int out_size)
{
    const float* x      = (const float*)d_in[0];
    const float* h      = (const float*)d_in[1];
    const float* c      = (const float*)d_in[2];
    const float* me     = (const float*)d_in[3];
    const float* W_ih   = (const float*)d_in[4];
    const float* W_hh   = (const float*)d_in[5];
    const float* bias   = (const float*)d_in[6];
    const float* W_memi = (const float*)d_in[7];
    const float* W_memh = (const float*)d_in[8];
    const float* W_memt = (const float*)d_in[9];
    const float* mem_b  = (const float*)d_in[10];
    float* out = (float*)d_out;

    cudaFuncSetAttribute(mma_gemm<0>, cudaFuncAttributeMaxDynamicSharedMemorySize, SMEM_BYTES);
    cudaFuncSetAttribute(mma_gemm<1>, cudaFuncAttributeMaxDynamicSharedMemorySize, SMEM_BYTES);
    cudaFuncSetAttribute(mma_gemm<2>, cudaFuncAttributeMaxDynamicSharedMemorySize, SMEM_BYTES);

    float *wt1, *wt2, *wt3;
    cudaGetSymbolAddress((void**)&wt1, g_Wt1);
    cudaGetSymbolAddress((void**)&wt2, g_Wt2);
    cudaGetSymbolAddress((void**)&wt3, g_Wt3);

    transpose_all<<<5888, dim3(32, 8)>>>(W_ih, W_hh, W_memi, W_memh, W_memt);

    mma_gemm<0><<<dim3(16, 128), 256, SMEM_BYTES>>>(
        x, 512, h, 512, 512, 1024, wt1, bias, nullptr, nullptr, nullptr, nullptr);

    mma_gemm<1><<<dim3(12, 128), 256, SMEM_BYTES>>>(
        x, 512, me, 1536, 512, 2048, wt2, mem_b, me, nullptr, nullptr, nullptr);

    mma_gemm<2><<<dim3(4, 128), 256, SMEM_BYTES>>>(
        nullptr, 1536, nullptr, 1536, 1536, 1536, wt3, nullptr, nullptr, c, h, out);
}